// round 1
// baseline (speedup 1.0000x reference)
#include <cuda_runtime.h>
#include <cuda_bf16.h>
#include <math.h>

#define Bq 4
#define Hh 16
#define Ss 2048
#define Dd 64
#define BM 128
#define BN 64
#define THREADS 256
#define SW 32            // mask words per row = Ss/32 = 64

// packed mask bits: [B][S][S/32], 2 MB scratch
__device__ unsigned g_maskbits[Bq * Ss * (Ss / 32)];

__global__ void pack_mask_kernel(const int* __restrict__ mask) {
    int gt = blockIdx.x * blockDim.x + threadIdx.x;   // one thread per mask element
    int val = (mask[gt] != 0);
    unsigned w = __ballot_sync(0xffffffffu, val);
    if ((threadIdx.x & 31) == 0) g_maskbits[gt >> 5] = w;
}

__device__ __forceinline__ float f2tff(float f) {
    unsigned u;
    asm("cvt.rna.tf32.f32 %0, %1;" : "=r"(u) : "f"(f));
    return __uint_as_float(u);
}

__device__ __forceinline__ void mma_tf32(float c[4],
                                         unsigned a0, unsigned a1, unsigned a2, unsigned a3,
                                         unsigned b0, unsigned b1) {
    asm volatile(
        "mma.sync.aligned.m16n8k8.row.col.f32.tf32.tf32.f32 "
        "{%0,%1,%2,%3},{%4,%5,%6,%7},{%8,%9},{%0,%1,%2,%3};\n"
        : "+f"(c[0]), "+f"(c[1]), "+f"(c[2]), "+f"(c[3])
        : "r"(a0), "r"(a1), "r"(a2), "r"(a3), "r"(b0), "r"(b1));
}

// smem float offsets
#define QS_OFF   0          // [128][68]
#define KS_OFF   8704       // [64][68]
#define VS_OFF   13056      // [64][72]
#define PS_OFF   17664      // [128][68]
#define RMAX_OFF 26368      // [128][2]
#define RSUM_OFF 26624      // [128][2]
#define SMEM_FLOATS 26880   // 107520 bytes

__device__ __forceinline__ void load_k_tile(float* Ks, const float* kbase, int kt, int tid) {
    #pragma unroll
    for (int it = 0; it < 4; it++) {
        int f4 = tid + it * THREADS;        // 1024 float4s total
        int row = f4 >> 4, c4 = f4 & 15;
        float4 v = *(const float4*)(kbase + (size_t)(kt * BN + row) * Dd + c4 * 4);
        float4 t;
        t.x = f2tff(v.x); t.y = f2tff(v.y); t.z = f2tff(v.z); t.w = f2tff(v.w);
        *(float4*)(Ks + row * 68 + c4 * 4) = t;
    }
}

__device__ __forceinline__ void load_v_tile(float* Vs, const float* vbase, int kt, int tid) {
    #pragma unroll
    for (int it = 0; it < 4; it++) {
        int f4 = tid + it * THREADS;
        int row = f4 >> 4, c4 = f4 & 15;
        float4 v = *(const float4*)(vbase + (size_t)(kt * BN + row) * Dd + c4 * 4);
        float4 t;
        t.x = f2tff(v.x); t.y = f2tff(v.y); t.z = f2tff(v.z); t.w = f2tff(v.w);
        *(float4*)(Vs + row * 72 + c4 * 4) = t;
    }
}

// QK^T for this warp's 32x32 sub-tile -> sacc
__device__ __forceinline__ void qk_mma(float sacc[2][4][4], const float* Qs, const float* Ks,
                                       int r0, int g, int qd, int wn) {
    #pragma unroll
    for (int i = 0; i < 2; i++)
        #pragma unroll
        for (int j = 0; j < 4; j++)
            #pragma unroll
            for (int c = 0; c < 4; c++) sacc[i][j][c] = 0.f;

    #pragma unroll
    for (int ks = 0; ks < 8; ks++) {
        unsigned a[2][4];
        #pragma unroll
        for (int i = 0; i < 2; i++) {
            const float* qr = Qs + (r0 + 16 * i + g) * 68 + qd + 8 * ks;
            a[i][0] = __float_as_uint(qr[0]);
            a[i][1] = __float_as_uint(qr[8 * 68]);
            a[i][2] = __float_as_uint(qr[4]);
            a[i][3] = __float_as_uint(qr[8 * 68 + 4]);
        }
        #pragma unroll
        for (int j = 0; j < 4; j++) {
            const float* kr = Ks + (wn * 32 + 8 * j + g) * 68 + qd + 8 * ks;
            unsigned b0 = __float_as_uint(kr[0]);
            unsigned b1 = __float_as_uint(kr[4]);
            #pragma unroll
            for (int i = 0; i < 2; i++)
                mma_tf32(sacc[i][j], a[i][0], a[i][1], a[i][2], a[i][3], b0, b1);
        }
    }
}

__global__ __launch_bounds__(THREADS, 2)
void attn_kernel(const float* __restrict__ Qg, const float* __restrict__ Kg,
                 const float* __restrict__ Vg, float* __restrict__ Og,
                 float* __restrict__ Pg) {
    extern __shared__ float sm[];
    float* Qs   = sm + QS_OFF;
    float* Ks   = sm + KS_OFF;
    float* Vs   = sm + VS_OFF;
    float* Ps   = sm + PS_OFF;
    float* Rmax = sm + RMAX_OFF;
    float* Rsum = sm + RSUM_OFF;

    const int tid  = threadIdx.x;
    const int lane = tid & 31;
    const int warp = tid >> 5;
    const int g    = lane >> 2;      // groupID 0..7
    const int qd   = lane & 3;       // threadID in group 0..3
    const int wm   = warp >> 1;      // 0..3  (q-row block)
    const int wn   = warp & 1;       // 0..1  (k-col / d-col half)
    const int r0   = wm * 32;

    const int hh = blockIdx.x, qt = blockIdx.y, bb = blockIdx.z;
    const size_t bh = (size_t)(bb * Hh + hh);
    const float* qptr  = Qg + (bh * Ss + (size_t)qt * BM) * Dd;
    const float* kbase = Kg + bh * Ss * Dd;
    const float* vbase = Vg + bh * Ss * Dd;
    const unsigned* mbase = g_maskbits + ((size_t)bb * Ss + (size_t)qt * BM) * (Ss / 32);

    const float scale = 0.125f;   // 1/sqrt(64)

    // ---- load Q tile (128x64) as tf32 ----
    #pragma unroll
    for (int it = 0; it < 8; it++) {
        int f4 = tid + it * THREADS;     // 2048 float4s
        int row = f4 >> 4, c4 = f4 & 15;
        float4 v = *(const float4*)(qptr + (size_t)row * Dd + c4 * 4);
        float4 t;
        t.x = f2tff(v.x); t.y = f2tff(v.y); t.z = f2tff(v.z); t.w = f2tff(v.w);
        *(float4*)(Qs + row * 68 + c4 * 4) = t;
    }

    float m[2][2], l[2][2];
    #pragma unroll
    for (int i = 0; i < 2; i++)
        #pragma unroll
        for (int r = 0; r < 2; r++) { m[i][r] = -1e30f; l[i][r] = 0.f; }

    float sacc[2][4][4];

    // ================= Phase A: row stats (max, sumexp) =================
    for (int kt = 0; kt < Ss / BN; kt++) {
        load_k_tile(Ks, kbase, kt, tid);
        __syncthreads();

        qk_mma(sacc, Qs, Ks, r0, g, qd, wn);

        // mask + scale
        unsigned mw[2][2];
        #pragma unroll
        for (int i = 0; i < 2; i++)
            #pragma unroll
            for (int r = 0; r < 2; r++)
                mw[i][r] = mbase[(size_t)(r0 + 16 * i + g + 8 * r) * SW * 2 + kt * 2 + wn];
        #pragma unroll
        for (int i = 0; i < 2; i++)
            #pragma unroll
            for (int j = 0; j < 4; j++) {
                int lc = 8 * j + 2 * qd;
                #pragma unroll
                for (int c = 0; c < 4; c++) {
                    int col = lc + (c & 1);
                    int r = c >> 1;
                    float s = sacc[i][j][c] * scale;
                    sacc[i][j][c] = ((mw[i][r] >> col) & 1u) ? s : 1e-12f;
                }
            }

        // per-row max (intra-warp half), publish to smem
        #pragma unroll
        for (int i = 0; i < 2; i++)
            #pragma unroll
            for (int r = 0; r < 2; r++) {
                float t = -1e30f;
                #pragma unroll
                for (int j = 0; j < 4; j++)
                    t = fmaxf(t, fmaxf(sacc[i][j][2 * r], sacc[i][j][2 * r + 1]));
                t = fmaxf(t, __shfl_xor_sync(0xffffffffu, t, 1));
                t = fmaxf(t, __shfl_xor_sync(0xffffffffu, t, 2));
                if (qd == 0) Rmax[(r0 + 16 * i + g + 8 * r) * 2 + wn] = t;
            }
        __syncthreads();

        float corr[2][2];
        #pragma unroll
        for (int i = 0; i < 2; i++)
            #pragma unroll
            for (int r = 0; r < 2; r++) {
                int row = r0 + 16 * i + g + 8 * r;
                float tm = fmaxf(Rmax[row * 2], Rmax[row * 2 + 1]);
                float mn = fmaxf(m[i][r], tm);
                corr[i][r] = __expf(m[i][r] - mn);
                m[i][r] = mn;
                float ps = 0.f;
                #pragma unroll
                for (int j = 0; j < 4; j++)
                    ps += __expf(sacc[i][j][2 * r] - mn) + __expf(sacc[i][j][2 * r + 1] - mn);
                ps += __shfl_xor_sync(0xffffffffu, ps, 1);
                ps += __shfl_xor_sync(0xffffffffu, ps, 2);
                if (qd == 0) Rsum[row * 2 + wn] = ps;
            }
        __syncthreads();

        #pragma unroll
        for (int i = 0; i < 2; i++)
            #pragma unroll
            for (int r = 0; r < 2; r++) {
                int row = r0 + 16 * i + g + 8 * r;
                l[i][r] = l[i][r] * corr[i][r] + Rsum[row * 2] + Rsum[row * 2 + 1];
            }
        // next-iteration load sync doubles as the write/read fence for Rsum
    }

    float inv_l[2][2];
    #pragma unroll
    for (int i = 0; i < 2; i++)
        #pragma unroll
        for (int r = 0; r < 2; r++) inv_l[i][r] = 1.0f / l[i][r];

    float oacc[2][4][4];
    #pragma unroll
    for (int i = 0; i < 2; i++)
        #pragma unroll
        for (int j = 0; j < 4; j++)
            #pragma unroll
            for (int c = 0; c < 4; c++) oacc[i][j][c] = 0.f;

    float* score = Pg + bh * (size_t)Ss * Ss + (size_t)(qt * BM) * Ss;

    // ================= Phase B: recompute, write p, accumulate O =================
    for (int kt = 0; kt < Ss / BN; kt++) {
        load_k_tile(Ks, kbase, kt, tid);
        load_v_tile(Vs, vbase, kt, tid);
        __syncthreads();

        qk_mma(sacc, Qs, Ks, r0, g, qd, wn);

        #pragma unroll
        for (int i = 0; i < 2; i++) {
            unsigned mw0 = mbase[(size_t)(r0 + 16 * i + g) * SW * 2 + kt * 2 + wn];
            unsigned mw1 = mbase[(size_t)(r0 + 16 * i + g + 8) * SW * 2 + kt * 2 + wn];
            #pragma unroll
            for (int j = 0; j < 4; j++) {
                int lc = 8 * j + 2 * qd;
                float s0 = ((mw0 >> lc) & 1u)       ? sacc[i][j][0] * scale : 1e-12f;
                float s1 = ((mw0 >> (lc + 1)) & 1u) ? sacc[i][j][1] * scale : 1e-12f;
                float s2 = ((mw1 >> lc) & 1u)       ? sacc[i][j][2] * scale : 1e-12f;
                float s3 = ((mw1 >> (lc + 1)) & 1u) ? sacc[i][j][3] * scale : 1e-12f;
                float p0 = __expf(s0 - m[i][0]) * inv_l[i][0];
                float p1 = __expf(s1 - m[i][0]) * inv_l[i][0];
                float p2 = __expf(s2 - m[i][1]) * inv_l[i][1];
                float p3 = __expf(s3 - m[i][1]) * inv_l[i][1];
                int row0 = r0 + 16 * i + g, row1 = row0 + 8;
                int gcol = kt * BN + wn * 32 + lc;
                __stcs((float2*)(score + (size_t)row0 * Ss + gcol), make_float2(p0, p1));
                __stcs((float2*)(score + (size_t)row1 * Ss + gcol), make_float2(p2, p3));
                *(float2*)(Ps + row0 * 68 + wn * 32 + lc) = make_float2(f2tff(p0), f2tff(p1));
                *(float2*)(Ps + row1 * 68 + wn * 32 + lc) = make_float2(f2tff(p2), f2tff(p3));
            }
        }
        __syncthreads();   // Ps complete (both n-half warps)

        // P @ V  (A = Ps rows [r0,r0+32) x keys 64, B = Vs keys x d-half)
        #pragma unroll
        for (int kk = 0; kk < 8; kk++) {
            unsigned a[2][4];
            #pragma unroll
            for (int i = 0; i < 2; i++) {
                const float* pr = Ps + (r0 + 16 * i + g) * 68 + qd + 8 * kk;
                a[i][0] = __float_as_uint(pr[0]);
                a[i][1] = __float_as_uint(pr[8 * 68]);
                a[i][2] = __float_as_uint(pr[4]);
                a[i][3] = __float_as_uint(pr[8 * 68 + 4]);
            }
            #pragma unroll
            for (int j = 0; j < 4; j++) {
                const float* vr = Vs + (qd + 8 * kk) * 72 + wn * 32 + 8 * j + g;
                unsigned b0 = __float_as_uint(vr[0]);
                unsigned b1 = __float_as_uint(vr[4 * 72]);
                #pragma unroll
                for (int i = 0; i < 2; i++)
                    mma_tf32(oacc[i][j], a[i][0], a[i][1], a[i][2], a[i][3], b0, b1);
            }
        }
        __syncthreads();   // everyone done with Vs/Ps before next tile load
    }

    // ---- write O ----
    float* optr = Og + (bh * Ss + (size_t)qt * BM) * Dd;
    #pragma unroll
    for (int i = 0; i < 2; i++)
        #pragma unroll
        for (int j = 0; j < 4; j++) {
            int row0 = r0 + 16 * i + g;
            int col = wn * 32 + 8 * j + 2 * qd;
            *(float2*)(optr + (size_t)row0 * Dd + col) =
                make_float2(oacc[i][j][0], oacc[i][j][1]);
            *(float2*)(optr + (size_t)(row0 + 8) * Dd + col) =
                make_float2(oacc[i][j][2], oacc[i][j][3]);
        }
}

extern "C" void kernel_launch(void* const* d_in, const int* in_sizes, int n_in,
                              void* d_out, int out_size) {
    const float* q = (const float*)d_in[0];
    const float* k = (const float*)d_in[1];
    const float* v = (const float*)d_in[2];
    const int* mask = (const int*)d_in[3];

    float* out = (float*)d_out;
    float* score = out + (size_t)Bq * Hh * Ss * Dd;   // output first, then score

    // 1. pack mask into bitwords (2 MB device scratch)
    {
        int total = Bq * Ss * Ss;          // 16,777,216 elements
        pack_mask_kernel<<<total / 256, 256>>>(mask);
    }

    // 2. fused attention
    size_t smem = SMEM_FLOATS * sizeof(float);   // 107,520 B
    cudaFuncSetAttribute(attn_kernel, cudaFuncAttributeMaxDynamicSharedMemorySize, (int)smem);
    dim3 grid(Hh, Ss / BM, Bq);   // heads fastest -> same-batch mask rows reused in L2
    attn_kernel<<<grid, THREADS, smem>>>(q, k, v, out, score);
}

// round 2
// speedup vs baseline: 1.0016x; 1.0016x over previous
#include <cuda_runtime.h>
#include <cuda_bf16.h>
#include <math.h>

#define Bq 4
#define Hh 16
#define Ss 2048
#define Dd 64
#define BM 128
#define BN 64
#define THREADS 256
#define SW 32            // mask words per row = Ss/32 = 64

// packed mask bits: [B][S][S/32], 2 MB scratch
__device__ unsigned g_maskbits[Bq * Ss * (Ss / 32)];

__global__ void pack_mask_kernel(const int* __restrict__ mask) {
    int gt = blockIdx.x * blockDim.x + threadIdx.x;   // one thread per mask element
    int val = (mask[gt] != 0);
    unsigned w = __ballot_sync(0xffffffffu, val);
    if ((threadIdx.x & 31) == 0) g_maskbits[gt >> 5] = w;
}

__device__ __forceinline__ float f2tff(float f) {
    unsigned u;
    asm("cvt.rna.tf32.f32 %0, %1;" : "=r"(u) : "f"(f));
    return __uint_as_float(u);
}

__device__ __forceinline__ void mma_tf32(float c[4],
                                         unsigned a0, unsigned a1, unsigned a2, unsigned a3,
                                         unsigned b0, unsigned b1) {
    asm volatile(
        "mma.sync.aligned.m16n8k8.row.col.f32.tf32.tf32.f32 "
        "{%0,%1,%2,%3},{%4,%5,%6,%7},{%8,%9},{%0,%1,%2,%3};\n"
        : "+f"(c[0]), "+f"(c[1]), "+f"(c[2]), "+f"(c[3])
        : "r"(a0), "r"(a1), "r"(a2), "r"(a3), "r"(b0), "r"(b1));
}

// smem float offsets
#define QS_OFF   0          // [128][68]
#define KS_OFF   8704       // [64][68]
#define VS_OFF   13056      // [64][72]
#define PS_OFF   17664      // [128][68]
#define RMAX_OFF 26368      // [128][2]
#define RSUM_OFF 26624      // [128][2]
#define SMEM_FLOATS 26880   // 107520 bytes

__device__ __forceinline__ void load_k_tile(float* Ks, const float* kbase, int kt, int tid) {
    #pragma unroll
    for (int it = 0; it < 4; it++) {
        int f4 = tid + it * THREADS;        // 1024 float4s total
        int row = f4 >> 4, c4 = f4 & 15;
        float4 v = *(const float4*)(kbase + (size_t)(kt * BN + row) * Dd + c4 * 4);
        float4 t;
        t.x = f2tff(v.x); t.y = f2tff(v.y); t.z = f2tff(v.z); t.w = f2tff(v.w);
        *(float4*)(Ks + row * 68 + c4 * 4) = t;
    }
}

__device__ __forceinline__ void load_v_tile(float* Vs, const float* vbase, int kt, int tid) {
    #pragma unroll
    for (int it = 0; it < 4; it++) {
        int f4 = tid + it * THREADS;
        int row = f4 >> 4, c4 = f4 & 15;
        float4 v = *(const float4*)(vbase + (size_t)(kt * BN + row) * Dd + c4 * 4);
        float4 t;
        t.x = f2tff(v.x); t.y = f2tff(v.y); t.z = f2tff(v.z); t.w = f2tff(v.w);
        *(float4*)(Vs + row * 72 + c4 * 4) = t;
    }
}

// QK^T for this warp's 32x32 sub-tile -> sacc
__device__ __forceinline__ void qk_mma(float sacc[2][4][4], const float* Qs, const float* Ks,
                                       int r0, int g, int qd, int wn) {
    #pragma unroll
    for (int i = 0; i < 2; i++)
        #pragma unroll
        for (int j = 0; j < 4; j++)
            #pragma unroll
            for (int c = 0; c < 4; c++) sacc[i][j][c] = 0.f;

    #pragma unroll
    for (int ks = 0; ks < 8; ks++) {
        unsigned a[2][4];
        #pragma unroll
        for (int i = 0; i < 2; i++) {
            const float* qr = Qs + (r0 + 16 * i + g) * 68 + qd + 8 * ks;
            a[i][0] = __float_as_uint(qr[0]);
            a[i][1] = __float_as_uint(qr[8 * 68]);
            a[i][2] = __float_as_uint(qr[4]);
            a[i][3] = __float_as_uint(qr[8 * 68 + 4]);
        }
        #pragma unroll
        for (int j = 0; j < 4; j++) {
            const float* kr = Ks + (wn * 32 + 8 * j + g) * 68 + qd + 8 * ks;
            unsigned b0 = __float_as_uint(kr[0]);
            unsigned b1 = __float_as_uint(kr[4]);
            #pragma unroll
            for (int i = 0; i < 2; i++)
                mma_tf32(sacc[i][j], a[i][0], a[i][1], a[i][2], a[i][3], b0, b1);
        }
    }
}

__global__ __launch_bounds__(THREADS, 2)
void attn_kernel(const float* __restrict__ Qg, const float* __restrict__ Kg,
                 const float* __restrict__ Vg, float* __restrict__ Og,
                 float* __restrict__ Pg) {
    extern __shared__ float sm[];
    float* Qs   = sm + QS_OFF;
    float* Ks   = sm + KS_OFF;
    float* Vs   = sm + VS_OFF;
    float* Ps   = sm + PS_OFF;
    float* Rmax = sm + RMAX_OFF;
    float* Rsum = sm + RSUM_OFF;

    const int tid  = threadIdx.x;
    const int lane = tid & 31;
    const int warp = tid >> 5;
    const int g    = lane >> 2;      // groupID 0..7
    const int qd   = lane & 3;       // threadID in group 0..3
    const int wm   = warp >> 1;      // 0..3  (q-row block)
    const int wn   = warp & 1;       // 0..1  (k-col / d-col half)
    const int r0   = wm * 32;

    const int hh = blockIdx.x, qt = blockIdx.y, bb = blockIdx.z;
    const size_t bh = (size_t)(bb * Hh + hh);
    const float* qptr  = Qg + (bh * Ss + (size_t)qt * BM) * Dd;
    const float* kbase = Kg + bh * Ss * Dd;
    const float* vbase = Vg + bh * Ss * Dd;
    const unsigned* mbase = g_maskbits + ((size_t)bb * Ss + (size_t)qt * BM) * (Ss / 32);

    const float scale = 0.125f;   // 1/sqrt(64)

    // ---- load Q tile (128x64) as tf32 ----
    #pragma unroll
    for (int it = 0; it < 8; it++) {
        int f4 = tid + it * THREADS;     // 2048 float4s
        int row = f4 >> 4, c4 = f4 & 15;
        float4 v = *(const float4*)(qptr + (size_t)row * Dd + c4 * 4);
        float4 t;
        t.x = f2tff(v.x); t.y = f2tff(v.y); t.z = f2tff(v.z); t.w = f2tff(v.w);
        *(float4*)(Qs + row * 68 + c4 * 4) = t;
    }

    float m[2][2], l[2][2];
    #pragma unroll
    for (int i = 0; i < 2; i++)
        #pragma unroll
        for (int r = 0; r < 2; r++) { m[i][r] = -1e30f; l[i][r] = 0.f; }

    float sacc[2][4][4];

    // ================= Phase A: row stats (max, sumexp) =================
    for (int kt = 0; kt < Ss / BN; kt++) {
        load_k_tile(Ks, kbase, kt, tid);
        __syncthreads();

        qk_mma(sacc, Qs, Ks, r0, g, qd, wn);

        // mask + scale
        unsigned mw[2][2];
        #pragma unroll
        for (int i = 0; i < 2; i++)
            #pragma unroll
            for (int r = 0; r < 2; r++)
                mw[i][r] = mbase[(size_t)(r0 + 16 * i + g + 8 * r) * SW * 2 + kt * 2 + wn];
        #pragma unroll
        for (int i = 0; i < 2; i++)
            #pragma unroll
            for (int j = 0; j < 4; j++) {
                int lc = 8 * j + 2 * qd;
                #pragma unroll
                for (int c = 0; c < 4; c++) {
                    int col = lc + (c & 1);
                    int r = c >> 1;
                    float s = sacc[i][j][c] * scale;
                    sacc[i][j][c] = ((mw[i][r] >> col) & 1u) ? s : 1e-12f;
                }
            }

        // per-row max (intra-warp half), publish to smem
        #pragma unroll
        for (int i = 0; i < 2; i++)
            #pragma unroll
            for (int r = 0; r < 2; r++) {
                float t = -1e30f;
                #pragma unroll
                for (int j = 0; j < 4; j++)
                    t = fmaxf(t, fmaxf(sacc[i][j][2 * r], sacc[i][j][2 * r + 1]));
                t = fmaxf(t, __shfl_xor_sync(0xffffffffu, t, 1));
                t = fmaxf(t, __shfl_xor_sync(0xffffffffu, t, 2));
                if (qd == 0) Rmax[(r0 + 16 * i + g + 8 * r) * 2 + wn] = t;
            }
        __syncthreads();

        float corr[2][2];
        #pragma unroll
        for (int i = 0; i < 2; i++)
            #pragma unroll
            for (int r = 0; r < 2; r++) {
                int row = r0 + 16 * i + g + 8 * r;
                float tm = fmaxf(Rmax[row * 2], Rmax[row * 2 + 1]);
                float mn = fmaxf(m[i][r], tm);
                corr[i][r] = __expf(m[i][r] - mn);
                m[i][r] = mn;
                float ps = 0.f;
                #pragma unroll
                for (int j = 0; j < 4; j++)
                    ps += __expf(sacc[i][j][2 * r] - mn) + __expf(sacc[i][j][2 * r + 1] - mn);
                ps += __shfl_xor_sync(0xffffffffu, ps, 1);
                ps += __shfl_xor_sync(0xffffffffu, ps, 2);
                if (qd == 0) Rsum[row * 2 + wn] = ps;
            }
        __syncthreads();

        #pragma unroll
        for (int i = 0; i < 2; i++)
            #pragma unroll
            for (int r = 0; r < 2; r++) {
                int row = r0 + 16 * i + g + 8 * r;
                l[i][r] = l[i][r] * corr[i][r] + Rsum[row * 2] + Rsum[row * 2 + 1];
            }
        // next-iteration load sync doubles as the write/read fence for Rsum
    }

    float inv_l[2][2];
    #pragma unroll
    for (int i = 0; i < 2; i++)
        #pragma unroll
        for (int r = 0; r < 2; r++) inv_l[i][r] = 1.0f / l[i][r];

    float oacc[2][4][4];
    #pragma unroll
    for (int i = 0; i < 2; i++)
        #pragma unroll
        for (int j = 0; j < 4; j++)
            #pragma unroll
            for (int c = 0; c < 4; c++) oacc[i][j][c] = 0.f;

    float* score = Pg + bh * (size_t)Ss * Ss + (size_t)(qt * BM) * Ss;

    // ================= Phase B: recompute, write p, accumulate O =================
    for (int kt = 0; kt < Ss / BN; kt++) {
        load_k_tile(Ks, kbase, kt, tid);
        load_v_tile(Vs, vbase, kt, tid);
        __syncthreads();

        qk_mma(sacc, Qs, Ks, r0, g, qd, wn);

        #pragma unroll
        for (int i = 0; i < 2; i++) {
            unsigned mw0 = mbase[(size_t)(r0 + 16 * i + g) * SW * 2 + kt * 2 + wn];
            unsigned mw1 = mbase[(size_t)(r0 + 16 * i + g + 8) * SW * 2 + kt * 2 + wn];
            #pragma unroll
            for (int j = 0; j < 4; j++) {
                int lc = 8 * j + 2 * qd;
                float s0 = ((mw0 >> lc) & 1u)       ? sacc[i][j][0] * scale : 1e-12f;
                float s1 = ((mw0 >> (lc + 1)) & 1u) ? sacc[i][j][1] * scale : 1e-12f;
                float s2 = ((mw1 >> lc) & 1u)       ? sacc[i][j][2] * scale : 1e-12f;
                float s3 = ((mw1 >> (lc + 1)) & 1u) ? sacc[i][j][3] * scale : 1e-12f;
                float p0 = __expf(s0 - m[i][0]) * inv_l[i][0];
                float p1 = __expf(s1 - m[i][0]) * inv_l[i][0];
                float p2 = __expf(s2 - m[i][1]) * inv_l[i][1];
                float p3 = __expf(s3 - m[i][1]) * inv_l[i][1];
                int row0 = r0 + 16 * i + g, row1 = row0 + 8;
                int gcol = kt * BN + wn * 32 + lc;
                __stcs((float2*)(score + (size_t)row0 * Ss + gcol), make_float2(p0, p1));
                __stcs((float2*)(score + (size_t)row1 * Ss + gcol), make_float2(p2, p3));
                *(float2*)(Ps + row0 * 68 + wn * 32 + lc) = make_float2(f2tff(p0), f2tff(p1));
                *(float2*)(Ps + row1 * 68 + wn * 32 + lc) = make_float2(f2tff(p2), f2tff(p3));
            }
        }
        __syncthreads();   // Ps complete (both n-half warps)

        // P @ V  (A = Ps rows [r0,r0+32) x keys 64, B = Vs keys x d-half)
        #pragma unroll
        for (int kk = 0; kk < 8; kk++) {
            unsigned a[2][4];
            #pragma unroll
            for (int i = 0; i < 2; i++) {
                const float* pr = Ps + (r0 + 16 * i + g) * 68 + qd + 8 * kk;
                a[i][0] = __float_as_uint(pr[0]);
                a[i][1] = __float_as_uint(pr[8 * 68]);
                a[i][2] = __float_as_uint(pr[4]);
                a[i][3] = __float_as_uint(pr[8 * 68 + 4]);
            }
            #pragma unroll
            for (int j = 0; j < 4; j++) {
                const float* vr = Vs + (qd + 8 * kk) * 72 + wn * 32 + 8 * j + g;
                unsigned b0 = __float_as_uint(vr[0]);
                unsigned b1 = __float_as_uint(vr[4 * 72]);
                #pragma unroll
                for (int i = 0; i < 2; i++)
                    mma_tf32(oacc[i][j], a[i][0], a[i][1], a[i][2], a[i][3], b0, b1);
            }
        }
        __syncthreads();   // everyone done with Vs/Ps before next tile load
    }

    // ---- write O ----
    float* optr = Og + (bh * Ss + (size_t)qt * BM) * Dd;
    #pragma unroll
    for (int i = 0; i < 2; i++)
        #pragma unroll
        for (int j = 0; j < 4; j++) {
            int row0 = r0 + 16 * i + g;
            int col = wn * 32 + 8 * j + 2 * qd;
            *(float2*)(optr + (size_t)row0 * Dd + col) =
                make_float2(oacc[i][j][0], oacc[i][j][1]);
            *(float2*)(optr + (size_t)(row0 + 8) * Dd + col) =
                make_float2(oacc[i][j][2], oacc[i][j][3]);
        }
}

extern "C" void kernel_launch(void* const* d_in, const int* in_sizes, int n_in,
                              void* d_out, int out_size) {
    const float* q = (const float*)d_in[0];
    const float* k = (const float*)d_in[1];
    const float* v = (const float*)d_in[2];
    const int* mask = (const int*)d_in[3];

    float* out = (float*)d_out;
    float* score = out + (size_t)Bq * Hh * Ss * Dd;   // output first, then score

    // 1. pack mask into bitwords (2 MB device scratch)
    {
        int total = Bq * Ss * Ss;          // 16,777,216 elements
        pack_mask_kernel<<<total / 256, 256>>>(mask);
    }

    // 2. fused attention
    size_t smem = SMEM_FLOATS * sizeof(float);   // 107,520 B
    cudaFuncSetAttribute(attn_kernel, cudaFuncAttributeMaxDynamicSharedMemorySize, (int)smem);
    dim3 grid(Hh, Ss / BM, Bq);   // heads fastest -> same-batch mask rows reused in L2
    attn_kernel<<<grid, THREADS, smem>>>(q, k, v, out, score);
}

// round 7
// speedup vs baseline: 1.1076x; 1.1058x over previous
#include <cuda_runtime.h>
#include <cstdint>

#define Bq 4
#define Hh 16
#define Ss 2048
#define Dd 64
#define BM 128
#define BN 64
#define NKT 32
#define THREADS 256
#define PADK 68
#define PADV 72
#define SCALE2 0.18033688011112043f   // (1/8) * log2(e)
#define FULLM 0xffffffffu

__device__ unsigned g_maskbits[Bq * Ss * (Ss / 32)];

__global__ void pack_mask_kernel(const int* __restrict__ mask) {
    int gt = blockIdx.x * blockDim.x + threadIdx.x;
    unsigned w = __ballot_sync(FULLM, mask[gt] != 0);
    if ((threadIdx.x & 31) == 0) g_maskbits[gt >> 5] = w;
}

__device__ __forceinline__ float f2tff(float f) {
    unsigned u; asm("cvt.rna.tf32.f32 %0, %1;" : "=r"(u) : "f"(f)); return __uint_as_float(u);
}
__device__ __forceinline__ unsigned f2tfu(float f) {
    unsigned u; asm("cvt.rna.tf32.f32 %0, %1;" : "=r"(u) : "f"(f)); return u;
}
__device__ __forceinline__ float ex2f(float x) {
    float y; asm("ex2.approx.f32 %0, %1;" : "=f"(y) : "f"(x)); return y;
}
__device__ __forceinline__ uint32_t smem_u32(const void* p) {
    uint32_t a;
    asm("{ .reg .u64 t; cvta.to.shared.u64 t, %1; cvt.u32.u64 %0, t; }" : "=r"(a) : "l"(p));
    return a;
}
__device__ __forceinline__ void cpa16(uint32_t d, const float* s) {
    asm volatile("cp.async.cg.shared.global [%0], [%1], 16;" :: "r"(d), "l"(s));
}
__device__ __forceinline__ void cpacommit() { asm volatile("cp.async.commit_group;" ::: "memory"); }
template<int N> __device__ __forceinline__ void cpawait() {
    asm volatile("cp.async.wait_group %0;" :: "n"(N) : "memory");
}

__device__ __forceinline__ void mma_tf32(float c[4], const unsigned a[4], unsigned b0, unsigned b1) {
    asm volatile(
        "mma.sync.aligned.m16n8k8.row.col.f32.tf32.tf32.f32 "
        "{%0,%1,%2,%3},{%4,%5,%6,%7},{%8,%9},{%0,%1,%2,%3};\n"
        : "+f"(c[0]), "+f"(c[1]), "+f"(c[2]), "+f"(c[3])
        : "r"(a[0]), "r"(a[1]), "r"(a[2]), "r"(a[3]), "r"(b0), "r"(b1));
}

// smem float offsets
#define QS_OFF 0                       // 128 x 68 = 8704 (reused as O exchange in epilogue)
#define KS_OFF 8704                    // 3 bufs x 64 x 68
#define KBUF   4352
#define VS_OFF (KS_OFF + 3 * KBUF)     // 21760, 3 bufs x 64 x 72
#define VBUF   4608
#define RS_OFF (VS_OFF + 3 * VBUF)     // 35584, Rsum 128 x 2
#define SM_FLOATS (RS_OFF + 256)       // 35840 floats = 143360 B

__device__ __forceinline__ void stage_k(uint32_t sK, const float* kb, int kt, int tid) {
    #pragma unroll
    for (int i = 0; i < 4; i++) {
        int n = tid + i * THREADS;
        int row = n >> 4, c4 = n & 15;
        cpa16(sK + (unsigned)(row * PADK + c4 * 4) * 4u,
              kb + (size_t)(kt * BN + row) * Dd + c4 * 4);
    }
}
__device__ __forceinline__ void stage_v(uint32_t sV, const float* vb, int kt, int tid) {
    #pragma unroll
    for (int i = 0; i < 4; i++) {
        int n = tid + i * THREADS;
        int row = n >> 4, c4 = n & 15;
        cpa16(sV + (unsigned)(row * PADV + c4 * 4) * 4u,
              vb + (size_t)(kt * BN + row) * Dd + c4 * 4);
    }
}

__global__ __launch_bounds__(THREADS, 1)
void attn_kernel(const float* __restrict__ Qg, const float* __restrict__ Kg,
                 const float* __restrict__ Vg, float* __restrict__ Og,
                 float* __restrict__ Pg) {
    extern __shared__ float sm[];
    const uint32_t sb = smem_u32(sm);
    const int tid = threadIdx.x, lane = tid & 31, warp = tid >> 5;
    const int g = lane >> 2, qd = lane & 3, wm = warp >> 1, wn = warp & 1, r0 = wm * 32;

    const int hh = blockIdx.x, qt = blockIdx.y, bb = blockIdx.z;
    const size_t bh = (size_t)(bb * Hh + hh);
    const float* qptr  = Qg + (bh * Ss + (size_t)qt * BM) * Dd;
    const float* kbase = Kg + bh * Ss * Dd;
    const float* vbase = Vg + bh * Ss * Dd;
    float* score = Pg + bh * (size_t)Ss * Ss + (size_t)(qt * BM) * Ss;
    float* Og_t  = Og + (bh * Ss + (size_t)qt * BM) * Dd;

    // mask row pointers for this thread's 4 C-fragment rows
    const unsigned* mp[2][2];
    #pragma unroll
    for (int i = 0; i < 2; i++)
        #pragma unroll
        for (int r = 0; r < 2; r++) {
            int row = r0 + 16 * i + g + 8 * r;
            mp[i][r] = g_maskbits + ((size_t)bb * Ss + (size_t)qt * BM + row) * (Ss / 32);
        }

    // ---- stage Q once (tf32), then lift fragments into registers ----
    #pragma unroll
    for (int it = 0; it < 8; it++) {
        int n = tid + it * THREADS;
        int row = n >> 4, c4 = n & 15;
        float4 v = *(const float4*)(qptr + (size_t)row * Dd + c4 * 4);
        float4 t; t.x = f2tff(v.x); t.y = f2tff(v.y); t.z = f2tff(v.z); t.w = f2tff(v.w);
        *(float4*)(sm + QS_OFF + row * PADK + c4 * 4) = t;
    }
    __syncthreads();

    unsigned qf[2][8][4];   // Q fragments, resident for the whole kernel
    #pragma unroll
    for (int i = 0; i < 2; i++)
        #pragma unroll
        for (int ks = 0; ks < 8; ks++) {
            const float* qr = sm + QS_OFF + (r0 + 16 * i + g) * PADK + qd + 8 * ks;
            qf[i][ks][0] = __float_as_uint(qr[0]);
            qf[i][ks][1] = __float_as_uint(qr[8 * PADK]);
            qf[i][ks][2] = __float_as_uint(qr[4]);
            qf[i][ks][3] = __float_as_uint(qr[8 * PADK + 4]);
        }
    __syncthreads();

    // ================= Phase A: row sums of exp =================
    float lacc[2][2] = {{0.f, 0.f}, {0.f, 0.f}};

    stage_k(sb + (unsigned)(KS_OFF + 0 * KBUF) * 4u, kbase, 0, tid); cpacommit();
    stage_k(sb + (unsigned)(KS_OFF + 1 * KBUF) * 4u, kbase, 1, tid); cpacommit();

    for (int kt = 0; kt < NKT; kt++) {
        if (kt == NKT - 1) cpawait<0>(); else cpawait<1>();
        __syncthreads();
        if (kt + 2 < NKT) {
            stage_k(sb + (unsigned)(KS_OFF + ((kt + 2) % 3) * KBUF) * 4u, kbase, kt + 2, tid);
            cpacommit();
        }
        const float* Kb = sm + KS_OFF + (kt % 3) * KBUF;

        float sacc[2][4][4];
        #pragma unroll
        for (int i = 0; i < 2; i++)
            #pragma unroll
            for (int j = 0; j < 4; j++)
                #pragma unroll
                for (int c = 0; c < 4; c++) sacc[i][j][c] = 0.f;

        #pragma unroll
        for (int ks = 0; ks < 8; ks++)
            #pragma unroll
            for (int j = 0; j < 4; j++) {
                const float* kr = Kb + (wn * 32 + 8 * j + g) * PADK + qd + 8 * ks;
                unsigned b0 = f2tfu(kr[0]), b1 = f2tfu(kr[4]);
                mma_tf32(sacc[0][j], qf[0][ks], b0, b1);
                mma_tf32(sacc[1][j], qf[1][ks], b0, b1);
            }

        unsigned mw[2][2];
        #pragma unroll
        for (int i = 0; i < 2; i++)
            #pragma unroll
            for (int r = 0; r < 2; r++) mw[i][r] = mp[i][r][kt * 2 + wn];

        #pragma unroll
        for (int i = 0; i < 2; i++)
            #pragma unroll
            for (int j = 0; j < 4; j++) {
                int b = 8 * j + 2 * qd;
                lacc[i][0] += ex2f(((mw[i][0] >> b) & 1u)       ? sacc[i][j][0] * SCALE2 : 0.f);
                lacc[i][0] += ex2f(((mw[i][0] >> (b + 1)) & 1u) ? sacc[i][j][1] * SCALE2 : 0.f);
                lacc[i][1] += ex2f(((mw[i][1] >> b) & 1u)       ? sacc[i][j][2] * SCALE2 : 0.f);
                lacc[i][1] += ex2f(((mw[i][1] >> (b + 1)) & 1u) ? sacc[i][j][3] * SCALE2 : 0.f);
            }
    }

    // reduce l across qd group, then across wn halves via smem (once)
    #pragma unroll
    for (int i = 0; i < 2; i++)
        #pragma unroll
        for (int r = 0; r < 2; r++) {
            float v = lacc[i][r];
            v += __shfl_xor_sync(FULLM, v, 1);
            v += __shfl_xor_sync(FULLM, v, 2);
            if (qd == 0) sm[RS_OFF + (r0 + 16 * i + g + 8 * r) * 2 + wn] = v;
        }
    __syncthreads();
    float linv[2][2];
    #pragma unroll
    for (int i = 0; i < 2; i++)
        #pragma unroll
        for (int r = 0; r < 2; r++) {
            int row = r0 + 16 * i + g + 8 * r;
            linv[i][r] = 1.0f / (sm[RS_OFF + row * 2] + sm[RS_OFF + row * 2 + 1]);
        }
    __syncthreads();

    // ================= Phase B: recompute, write p, split-key PV =================
    float oacc[2][8][4];
    #pragma unroll
    for (int i = 0; i < 2; i++)
        #pragma unroll
        for (int jn = 0; jn < 8; jn++)
            #pragma unroll
            for (int c = 0; c < 4; c++) oacc[i][jn][c] = 0.f;

    stage_k(sb + (unsigned)(KS_OFF + 0 * KBUF) * 4u, kbase, 0, tid);
    stage_v(sb + (unsigned)(VS_OFF + 0 * VBUF) * 4u, vbase, 0, tid); cpacommit();
    stage_k(sb + (unsigned)(KS_OFF + 1 * KBUF) * 4u, kbase, 1, tid);
    stage_v(sb + (unsigned)(VS_OFF + 1 * VBUF) * 4u, vbase, 1, tid); cpacommit();

    const int srcA = (lane & ~3) | (qd >> 1);
    const int srcB = srcA + 2;

    for (int kt = 0; kt < NKT; kt++) {
        if (kt == NKT - 1) cpawait<0>(); else cpawait<1>();
        __syncthreads();
        if (kt + 2 < NKT) {
            stage_k(sb + (unsigned)(KS_OFF + ((kt + 2) % 3) * KBUF) * 4u, kbase, kt + 2, tid);
            stage_v(sb + (unsigned)(VS_OFF + ((kt + 2) % 3) * VBUF) * 4u, vbase, kt + 2, tid);
            cpacommit();
        }
        const float* Kb = sm + KS_OFF + (kt % 3) * KBUF;
        const float* Vb = sm + VS_OFF + (kt % 3) * VBUF;

        float sacc[2][4][4];
        #pragma unroll
        for (int i = 0; i < 2; i++)
            #pragma unroll
            for (int j = 0; j < 4; j++)
                #pragma unroll
                for (int c = 0; c < 4; c++) sacc[i][j][c] = 0.f;

        #pragma unroll
        for (int ks = 0; ks < 8; ks++)
            #pragma unroll
            for (int j = 0; j < 4; j++) {
                const float* kr = Kb + (wn * 32 + 8 * j + g) * PADK + qd + 8 * ks;
                unsigned b0 = f2tfu(kr[0]), b1 = f2tfu(kr[4]);
                mma_tf32(sacc[0][j], qf[0][ks], b0, b1);
                mma_tf32(sacc[1][j], qf[1][ks], b0, b1);
            }

        unsigned mw[2][2];
        #pragma unroll
        for (int i = 0; i < 2; i++)
            #pragma unroll
            for (int r = 0; r < 2; r++) mw[i][r] = mp[i][r][kt * 2 + wn];

        // p (normalized), streamed to gmem, then converted in place for PV
        #pragma unroll
        for (int i = 0; i < 2; i++)
            #pragma unroll
            for (int j = 0; j < 4; j++) {
                int b = 8 * j + 2 * qd;
                float p0 = ex2f(((mw[i][0] >> b) & 1u)       ? sacc[i][j][0] * SCALE2 : 0.f) * linv[i][0];
                float p1 = ex2f(((mw[i][0] >> (b + 1)) & 1u) ? sacc[i][j][1] * SCALE2 : 0.f) * linv[i][0];
                float p2 = ex2f(((mw[i][1] >> b) & 1u)       ? sacc[i][j][2] * SCALE2 : 0.f) * linv[i][1];
                float p3 = ex2f(((mw[i][1] >> (b + 1)) & 1u) ? sacc[i][j][3] * SCALE2 : 0.f) * linv[i][1];
                int gcol = kt * 64 + wn * 32 + b;
                __stcs((float2*)(score + (size_t)(r0 + 16 * i + g) * Ss + gcol), make_float2(p0, p1));
                __stcs((float2*)(score + (size_t)(r0 + 16 * i + g + 8) * Ss + gcol), make_float2(p2, p3));
                sacc[i][j][0] = f2tff(p0); sacc[i][j][1] = f2tff(p1);
                sacc[i][j][2] = f2tff(p2); sacc[i][j][3] = f2tff(p3);
            }

        // split-key PV: C-frag -> A-frag via shuffles (columns redistribute in 4-thread group)
        #pragma unroll
        for (int kk = 0; kk < 4; kk++) {
            unsigned a[2][4];
            #pragma unroll
            for (int i = 0; i < 2; i++) {
                float c0 = sacc[i][kk][0], c1 = sacc[i][kk][1];
                float c2 = sacc[i][kk][2], c3 = sacc[i][kk][3];
                float s0a = __shfl_sync(FULLM, c0, srcA), s1a = __shfl_sync(FULLM, c1, srcA);
                float s2a = __shfl_sync(FULLM, c2, srcA), s3a = __shfl_sync(FULLM, c3, srcA);
                float s0b = __shfl_sync(FULLM, c0, srcB), s1b = __shfl_sync(FULLM, c1, srcB);
                float s2b = __shfl_sync(FULLM, c2, srcB), s3b = __shfl_sync(FULLM, c3, srcB);
                a[i][0] = __float_as_uint((qd & 1) ? s1a : s0a);
                a[i][1] = __float_as_uint((qd & 1) ? s3a : s2a);
                a[i][2] = __float_as_uint((qd & 1) ? s1b : s0b);
                a[i][3] = __float_as_uint((qd & 1) ? s3b : s2b);
            }
            #pragma unroll
            for (int jn = 0; jn < 8; jn++) {
                const float* vr = Vb + (wn * 32 + 8 * kk + qd) * PADV + 8 * jn + g;
                unsigned b0 = f2tfu(vr[0]), b1 = f2tfu(vr[4 * PADV]);
                mma_tf32(oacc[0][jn], a[0], b0, b1);
                mma_tf32(oacc[1][jn], a[1], b0, b1);
            }
        }
    }

    // ---- epilogue: combine the two key-half partial O's (reuse Q smem) ----
    if (wn == 1) {
        #pragma unroll
        for (int i = 0; i < 2; i++)
            #pragma unroll
            for (int jn = 0; jn < 8; jn++) {
                int row = r0 + 16 * i + g, col = 8 * jn + 2 * qd;
                *(float2*)(sm + QS_OFF + row * PADK + col) =
                    make_float2(oacc[i][jn][0], oacc[i][jn][1]);
                *(float2*)(sm + QS_OFF + (row + 8) * PADK + col) =
                    make_float2(oacc[i][jn][2], oacc[i][jn][3]);
            }
    }
    __syncthreads();
    if (wn == 0) {
        #pragma unroll
        for (int i = 0; i < 2; i++)
            #pragma unroll
            for (int jn = 0; jn < 8; jn++) {
                int row = r0 + 16 * i + g, col = 8 * jn + 2 * qd;
                float o0 = oacc[i][jn][0] + sm[QS_OFF + row * PADK + col];
                float o1 = oacc[i][jn][1] + sm[QS_OFF + row * PADK + col + 1];
                float o2 = oacc[i][jn][2] + sm[QS_OFF + (row + 8) * PADK + col];
                float o3 = oacc[i][jn][3] + sm[QS_OFF + (row + 8) * PADK + col + 1];
                *(float2*)(Og_t + (size_t)row * Dd + col) = make_float2(o0, o1);
                *(float2*)(Og_t + (size_t)(row + 8) * Dd + col) = make_float2(o2, o3);
            }
    }
}

extern "C" void kernel_launch(void* const* d_in, const int* in_sizes, int n_in,
                              void* d_out, int out_size) {
    const float* q = (const float*)d_in[0];
    const float* k = (const float*)d_in[1];
    const float* v = (const float*)d_in[2];
    const int* mask = (const int*)d_in[3];

    float* out = (float*)d_out;
    float* score = out + (size_t)Bq * Hh * Ss * Dd;   // output first, then score

    pack_mask_kernel<<<(Bq * Ss * Ss) / 256, 256>>>(mask);

    size_t smem = (size_t)SM_FLOATS * sizeof(float);  // 143360 B
    cudaFuncSetAttribute(attn_kernel, cudaFuncAttributeMaxDynamicSharedMemorySize, (int)smem);
    dim3 grid(Hh, Ss / BM, Bq);
    attn_kernel<<<grid, THREADS, smem>>>(q, k, v, out, score);
}